// round 2
// baseline (speedup 1.0000x reference)
#include <cuda_runtime.h>
#include <cuda_bf16.h>

// Problem constants (fixed by the reference)
static constexpr int BN = 262144;   // batch
static constexpr int KN = 3;        // centers per class
static constexpr int DN = 64;       // feature dim
static constexpr float TH_F  = 0.95f;
static constexpr float EPS_F = 1e-12f;

static constexpr int GRID = 1184;   // 148 SMs * 8 blocks -> single wave at 256 thr/block

// Global accumulators (zero-initialized at module load; reset by last block each run)
__device__ double g_sum_min    = 0.0;
__device__ double g_sum_masked = 0.0;
__device__ double g_cnt        = 0.0;
__device__ unsigned int g_done = 0u;

// Each warp handles 2 rows per iteration.
// lane = h*16 + sub : half h owns row (pair*2 + h), lane loads float4 #sub of that row.
// Warp-wide x load = 32 consecutive float4 = 512 contiguous bytes (fully coalesced).
__global__ void __launch_bounds__(256, 8)
dist_kernel(const float4* __restrict__ x4,
            const int*    __restrict__ labels,
            const float4* __restrict__ c4,
            float*        __restrict__ out)
{
    const int lane    = threadIdx.x & 31;
    const int sub     = lane & 15;
    const int h       = lane >> 4;
    const int warp_id = (blockIdx.x * blockDim.x + threadIdx.x) >> 5;
    const int nwarps  = (GRID * 256) >> 5;

    float acc_min = 0.f, acc_msk = 0.f, acc_cnt = 0.f;

    #pragma unroll 2
    for (int pair = warp_id; pair < BN / 2; pair += nwarps) {
        const int row = pair * 2 + h;

        // x: 512B contiguous per warp
        const float4 xv = x4[pair * 32 + lane];

        // label: 16 lanes hit the same address -> single sector per half
        const int lab = __ldg(&labels[row]);
        const float4* cb = c4 + (size_t)lab * (KN * (DN / 4));

        // 3 partial squared distances over this lane's 4 elements
        float p0, p1, p2;
        {
            float4 cv = __ldg(&cb[0 * (DN / 4) + sub]);
            float d0 = xv.x - cv.x, d1 = xv.y - cv.y;
            float d2 = xv.z - cv.z, d3 = xv.w - cv.w;
            p0 = d0 * d0 + d1 * d1 + d2 * d2 + d3 * d3;
        }
        {
            float4 cv = __ldg(&cb[1 * (DN / 4) + sub]);
            float d0 = xv.x - cv.x, d1 = xv.y - cv.y;
            float d2 = xv.z - cv.z, d3 = xv.w - cv.w;
            p1 = d0 * d0 + d1 * d1 + d2 * d2 + d3 * d3;
        }
        {
            float4 cv = __ldg(&cb[2 * (DN / 4) + sub]);
            float d0 = xv.x - cv.x, d1 = xv.y - cv.y;
            float d2 = xv.z - cv.z, d3 = xv.w - cv.w;
            p2 = d0 * d0 + d1 * d1 + d2 * d2 + d3 * d3;
        }

        // Reduce within the 16-lane half (xor offsets < 16 never cross halves)
        #pragma unroll
        for (int o = 1; o < 16; o <<= 1) {
            p0 += __shfl_xor_sync(0xffffffffu, p0, o);
            p1 += __shfl_xor_sync(0xffffffffu, p1, o);
            p2 += __shfl_xor_sync(0xffffffffu, p2, o);
        }

        if (sub == 0) {
            // two smallest of three + min
            const float mn  = fminf(fminf(p0, p1), p2);
            const float mx  = fmaxf(fmaxf(p0, p1), p2);
            const float mid = (p0 + p1 + p2) - mn - mx;

            const float a = mn  + EPS_F;
            const float b = mid + EPS_F;
            const float p = a / (a + b);                  // p <= 0.5, p > 0
            const float ent = -(p * log2f(p) + (1.f - p) * log2f(1.f - p));

            acc_min += mn;
            if (ent <= TH_F) { acc_msk += mn; acc_cnt += 1.f; }
        }
    }

    // Warp reduce
    #pragma unroll
    for (int o = 16; o > 0; o >>= 1) {
        acc_min += __shfl_xor_sync(0xffffffffu, acc_min, o);
        acc_msk += __shfl_xor_sync(0xffffffffu, acc_msk, o);
        acc_cnt += __shfl_xor_sync(0xffffffffu, acc_cnt, o);
    }

    // Block reduce
    __shared__ float sm[3][8];
    __shared__ bool  s_last;
    const int wib = threadIdx.x >> 5;
    if (lane == 0) { sm[0][wib] = acc_min; sm[1][wib] = acc_msk; sm[2][wib] = acc_cnt; }
    __syncthreads();

    if (threadIdx.x == 0) {
        float a = 0.f, b = 0.f, c = 0.f;
        #pragma unroll
        for (int i = 0; i < 8; i++) { a += sm[0][i]; b += sm[1][i]; c += sm[2][i]; }
        atomicAdd(&g_sum_min,    (double)a);
        atomicAdd(&g_sum_masked, (double)b);
        atomicAdd(&g_cnt,        (double)c);
        __threadfence();
        const unsigned int ticket = atomicAdd(&g_done, 1u);
        s_last = (ticket == (unsigned int)(GRID - 1));
    }
    __syncthreads();

    // Last block to finish: produce outputs and reset state for next graph replay
    if (s_last && threadIdx.x == 0) {
        __threadfence();
        const double smn = g_sum_min;
        const double smk = g_sum_masked;
        const double cnt = g_cnt;
        out[0] = (float)(smn / (double)BN);
        out[1] = (float)(smk / cnt);
        g_sum_min = 0.0; g_sum_masked = 0.0; g_cnt = 0.0;
        __threadfence();
        g_done = 0u;
    }
}

extern "C" void kernel_launch(void* const* d_in, const int* in_sizes, int n_in,
                              void* d_out, int out_size) {
    const float* x       = (const float*)d_in[0];   // [B, D] f32
    const int*   labels  = (const int*)  d_in[1];   // [B] i32
    const float* centers = (const float*)d_in[2];   // [C, K, D] f32

    dist_kernel<<<GRID, 256>>>((const float4*)x, labels,
                               (const float4*)centers, (float*)d_out);
}

// round 3
// speedup vs baseline: 1.2102x; 1.2102x over previous
#include <cuda_runtime.h>
#include <cuda_bf16.h>

// Problem constants (fixed by the reference)
static constexpr int BN = 262144;   // batch
static constexpr int KN = 3;        // centers per class
static constexpr int DN = 64;       // feature dim
static constexpr float TH_F  = 0.95f;
static constexpr float EPS_F = 1e-12f;

static constexpr int GRID = 2048;   // 16384 warps -> exactly 2 iters/warp (8 rows/iter)

// Global accumulators (zero-initialized at module load; reset by last block each run)
__device__ double g_sum_min    = 0.0;
__device__ double g_sum_masked = 0.0;
__device__ double g_cnt        = 0.0;
__device__ unsigned int g_done = 0u;

__device__ __forceinline__ float dist4(const float4 a, const float4 b) {
    const float d0 = a.x - b.x, d1 = a.y - b.y;
    const float d2 = a.z - b.z, d3 = a.w - b.w;
    return d0 * d0 + d1 * d1 + d2 * d2 + d3 * d3;
}

// 4 lanes per row, 8 rows per warp iteration.
// lane = r*4 + s: row r (0..7), quarter s (0..3).
// x load j covers float4 index s + 4j of the row -> every warp LDG is 8 dense
// 64B chunks (full sectors). Reduction over 4 lanes = 2 shfl steps.
__global__ void __launch_bounds__(256)
dist_kernel(const float4* __restrict__ x4,
            const int*    __restrict__ labels,
            const float4* __restrict__ c4,
            float*        __restrict__ out)
{
    const int lane    = threadIdx.x & 31;
    const int r       = lane >> 2;
    const int s       = lane & 3;
    const int warp_id = (blockIdx.x * blockDim.x + threadIdx.x) >> 5;
    const int nwarps  = (GRID * 256) >> 5;

    float acc_min = 0.f, acc_msk = 0.f, acc_cnt = 0.f;

    for (int it = warp_id; it < BN / 8; it += nwarps) {
        const int row = it * 8 + r;

        // x: 4 float4 per lane, warp-dense per instruction
        const float4* xb = x4 + (size_t)it * 128 + r * 16 + s;
        const float4 xv0 = __ldcs(xb + 0);
        const float4 xv1 = __ldcs(xb + 4);
        const float4 xv2 = __ldcs(xb + 8);
        const float4 xv3 = __ldcs(xb + 12);

        const int lab = __ldg(&labels[row]);
        const float4* cb = c4 + (size_t)lab * (KN * (DN / 4)) + s;

        float p0, p1, p2;
        {
            const float4 c0 = __ldg(cb + 0);
            const float4 c1 = __ldg(cb + 4);
            const float4 c2 = __ldg(cb + 8);
            const float4 c3 = __ldg(cb + 12);
            p0 = dist4(xv0, c0) + dist4(xv1, c1) + dist4(xv2, c2) + dist4(xv3, c3);
        }
        {
            const float4 c0 = __ldg(cb + 16);
            const float4 c1 = __ldg(cb + 20);
            const float4 c2 = __ldg(cb + 24);
            const float4 c3 = __ldg(cb + 28);
            p1 = dist4(xv0, c0) + dist4(xv1, c1) + dist4(xv2, c2) + dist4(xv3, c3);
        }
        {
            const float4 c0 = __ldg(cb + 32);
            const float4 c1 = __ldg(cb + 36);
            const float4 c2 = __ldg(cb + 40);
            const float4 c3 = __ldg(cb + 44);
            p2 = dist4(xv0, c0) + dist4(xv1, c1) + dist4(xv2, c2) + dist4(xv3, c3);
        }

        // Reduce within the 4-lane group (xor 1,2 never crosses groups)
        p0 += __shfl_xor_sync(0xffffffffu, p0, 1);
        p1 += __shfl_xor_sync(0xffffffffu, p1, 1);
        p2 += __shfl_xor_sync(0xffffffffu, p2, 1);
        p0 += __shfl_xor_sync(0xffffffffu, p0, 2);
        p1 += __shfl_xor_sync(0xffffffffu, p1, 2);
        p2 += __shfl_xor_sync(0xffffffffu, p2, 2);

        if (s == 0) {
            // two smallest of three + min
            const float mn  = fminf(fminf(p0, p1), p2);
            const float mx  = fmaxf(fmaxf(p0, p1), p2);
            const float mid = (p0 + p1 + p2) - mn - mx;

            const float a = mn  + EPS_F;
            const float b = mid + EPS_F;
            const float p = a / (a + b);                  // 0 < p <= 0.5
            const float ent = -(p * log2f(p) + (1.f - p) * log2f(1.f - p));

            acc_min += mn;
            if (ent <= TH_F) { acc_msk += mn; acc_cnt += 1.f; }
        }
    }

    // Warp reduce
    #pragma unroll
    for (int o = 16; o > 0; o >>= 1) {
        acc_min += __shfl_xor_sync(0xffffffffu, acc_min, o);
        acc_msk += __shfl_xor_sync(0xffffffffu, acc_msk, o);
        acc_cnt += __shfl_xor_sync(0xffffffffu, acc_cnt, o);
    }

    // Block reduce + one double atomic triple per block
    __shared__ float sm[3][8];
    __shared__ bool  s_last;
    const int wib = threadIdx.x >> 5;
    if (lane == 0) { sm[0][wib] = acc_min; sm[1][wib] = acc_msk; sm[2][wib] = acc_cnt; }
    __syncthreads();

    if (threadIdx.x == 0) {
        float a = 0.f, b = 0.f, c = 0.f;
        #pragma unroll
        for (int i = 0; i < 8; i++) { a += sm[0][i]; b += sm[1][i]; c += sm[2][i]; }
        atomicAdd(&g_sum_min,    (double)a);
        atomicAdd(&g_sum_masked, (double)b);
        atomicAdd(&g_cnt,        (double)c);
        __threadfence();
        const unsigned int ticket = atomicAdd(&g_done, 1u);
        s_last = (ticket == (unsigned int)(GRID - 1));
    }
    __syncthreads();

    // Last block: produce outputs and reset state for the next graph replay
    if (s_last && threadIdx.x == 0) {
        __threadfence();
        const double smn = g_sum_min;
        const double smk = g_sum_masked;
        const double cnt = g_cnt;
        out[0] = (float)(smn / (double)BN);
        out[1] = (float)(smk / cnt);
        g_sum_min = 0.0; g_sum_masked = 0.0; g_cnt = 0.0;
        __threadfence();
        g_done = 0u;
    }
}

extern "C" void kernel_launch(void* const* d_in, const int* in_sizes, int n_in,
                              void* d_out, int out_size) {
    const float* x       = (const float*)d_in[0];   // [B, D] f32
    const int*   labels  = (const int*)  d_in[1];   // [B] i32
    const float* centers = (const float*)d_in[2];   // [C, K, D] f32

    dist_kernel<<<GRID, 256>>>((const float4*)x, labels,
                               (const float4*)centers, (float*)d_out);
}